// round 3
// baseline (speedup 1.0000x reference)
#include <cuda_runtime.h>
#include <cuda_bf16.h>
#include <cstdint>

// Detector post-process, fused load+reduce with packed (value,class) smem slots.
//
// Inputs (metadata order):
//   d_in[0] box          float32  (N, HW, A, 4)
//   d_in[1] box_conf     float32  (N, HW, A, 1)
//   d_in[2] class_score  float32  (N, HW, A, 80)
//   d_in[3] prior        float32  (HW, A, 4)
//   d_in[4] feat_size    scalar
//
// Output (flat float32): [box_out (B*4) | probs (B) | class_index (B)]

#ifndef THRESHOLD
#define THRESHOLD 0.5f
#endif

#define TB 256          // threads = boxes per tile
#define SLOTS 20        // float4 slots per box (80 classes)
#define RSTRIDE 257     // slot-major padded stride (boxes dim), conflict-free LDS.64

__global__ __launch_bounds__(TB, 5) void detector_kernel(
    const float4* __restrict__ box,        // [B]
    const float*  __restrict__ conf,       // [B]
    const float4* __restrict__ score4,     // [B*20]
    const float4* __restrict__ prior,      // [prior_mod]
    const unsigned* __restrict__ feat_raw, // scalar
    float4* __restrict__ box_out,          // [B]
    float*  __restrict__ probs_out,        // [B]
    float*  __restrict__ cls_out,          // [B]
    int n_boxes, int prior_mod)
{
    // red[s * RSTRIDE + b] = packed best of slot s of box b
    __shared__ unsigned long long red[SLOTS * RSTRIDE];   // 41120 B
    __shared__ float sconf[TB];                           // 1 KB

    const int t = threadIdx.x;
    const int tile_box0 = blockIdx.x * TB;

    // stage confidences for this tile
    {
        int bi = tile_box0 + t;
        sconf[t] = (bi < n_boxes) ? conf[bi] : 0.0f;
    }
    __syncthreads();

    // ---- fused coalesced load + per-float4 reduce ----
    // tile source: TB*SLOTS contiguous float4; thread t handles g = k*TB + t.
    const float4* gsrc = score4 + (size_t)tile_box0 * SLOTS;
    const long long valid_g = (long long)(n_boxes - tile_box0) * SLOTS; // float4s valid in tile

    #pragma unroll
    for (int k = 0; k < SLOTS; k++) {
        int g = k * TB + t;
        if (g < valid_g) {
            float4 v = gsrc[g];
            int b = g / SLOTS;
            int s = g - b * SLOTS;
            float c = sconf[b];
            float p0 = c * v.x, p1 = c * v.y, p2 = c * v.z, p3 = c * v.w;
            // local argmax, strict > keeps earliest (first-occurrence ties)
            float bv = p0; int bc = 0;
            if (p1 > bv) { bv = p1; bc = 1; }
            if (p2 > bv) { bv = p2; bc = 2; }
            if (p3 > bv) { bv = p3; bc = 3; }
            int cls = s * 4 + bc;
            // pack: non-negative fp32 bits are order-monotonic; low field favors
            // smaller class index on exact value ties (matches jnp.argmax).
            unsigned long long pk =
                ((unsigned long long)__float_as_uint(bv) << 32) |
                (unsigned)(127 - cls);
            red[s * RSTRIDE + b] = pk;
        }
    }
    __syncthreads();

    const int i = tile_box0 + t;
    if (i >= n_boxes) return;

    // ---- per-box reduction over 20 packed slots (conflict-free LDS.64) ----
    unsigned long long best = red[t];
    #pragma unroll
    for (int j = 1; j < SLOTS; j++) {
        unsigned long long pk = red[j * RSTRIDE + t];
        if (pk > best) best = pk;
    }
    float prob = __uint_as_float((unsigned)(best >> 32));
    int cls = 127 - (int)(best & 0xFFu);

    // feat_size may arrive as int32 or float32 bits; decode robustly.
    unsigned fb = *feat_raw;
    float feat = (fb < 0x01000000u) ? (float)fb : __uint_as_float(fb);
    float inv_feat = 1.0f / feat;

    // ---- box decode ----
    float4 b4 = box[i];
    float4 p  = prior[i % prior_mod];
    float cx = b4.x + p.x;
    float cy = b4.y + p.y;
    float hw = 0.5f * (b4.z * p.z);
    float hh = 0.5f * (b4.w * p.w);

    float4 corners;
    corners.x = (cx - hw) * inv_feat;
    corners.y = (cy - hh) * inv_feat;
    corners.z = (cx + hw) * inv_feat;
    corners.w = (cy + hh) * inv_feat;

    bool m = prob > THRESHOLD;
    box_out[i]   = m ? corners : make_float4(0.f, 0.f, 0.f, 0.f);
    probs_out[i] = m ? prob : 0.0f;
    cls_out[i]   = (float)cls;
}

extern "C" void kernel_launch(void* const* d_in, const int* in_sizes, int n_in,
                              void* d_out, int out_size)
{
    const float4*   box    = (const float4*)d_in[0];
    const float*    conf   = (const float*)d_in[1];
    const float4*   score4 = (const float4*)d_in[2];
    const float4*   prior  = (const float4*)d_in[3];
    const unsigned* feat   = (const unsigned*)d_in[4];

    int n_boxes   = in_sizes[1];       // N*HW*A
    int prior_mod = in_sizes[3] / 4;   // HW*A

    float* out       = (float*)d_out;
    float4* box_out  = (float4*)out;
    float*  probs    = out + (size_t)n_boxes * 4;
    float*  cls      = out + (size_t)n_boxes * 5;

    int blocks = (n_boxes + TB - 1) / TB;
    detector_kernel<<<blocks, TB>>>(box, conf, score4, prior, feat,
                                    box_out, probs, cls,
                                    n_boxes, prior_mod);
}

// round 4
// speedup vs baseline: 1.3399x; 1.3399x over previous
#include <cuda_runtime.h>
#include <cuda_bf16.h>
#include <cstdint>

// Detector post-process: persistent blocks, cp.async double-buffered score
// staging, per-box argmax + box decode.
//
// Inputs (metadata order):
//   d_in[0] box          float32  (N, HW, A, 4)
//   d_in[1] box_conf     float32  (N, HW, A, 1)
//   d_in[2] class_score  float32  (N, HW, A, 80)
//   d_in[3] prior        float32  (HW, A, 4)
//   d_in[4] feat_size    scalar
//
// Output (flat float32): [box_out (B*4) | probs (B) | class_index (B)]

#ifndef THRESHOLD
#define THRESHOLD 0.5f
#endif

#define TB 128            // threads per block
#define BOXES_PER_TILE 64
#define SLOTS 20          // float4 per box (80 classes)
#define PAD 21            // padded f4 stride per box -> conflict-free LDS.128
#define TILE_F4 (BOXES_PER_TILE * SLOTS)   // 1280
#define F4_PER_THREAD (TILE_F4 / TB)       // 10

__device__ __forceinline__ void cp_async16(uint32_t saddr, const void* gptr) {
    asm volatile("cp.async.cg.shared.global [%0], [%1], 16;\n"
                 :: "r"(saddr), "l"(gptr) : "memory");
}
__device__ __forceinline__ void cp_commit() {
    asm volatile("cp.async.commit_group;\n" ::: "memory");
}
__device__ __forceinline__ void cp_wait1() {
    asm volatile("cp.async.wait_group 1;\n" ::: "memory");
}

__global__ __launch_bounds__(TB) void detector_kernel(
    const float4* __restrict__ box,
    const float*  __restrict__ conf,
    const float4* __restrict__ score4,     // [B*20]
    const float4* __restrict__ prior,
    const unsigned* __restrict__ feat_raw,
    float4* __restrict__ box_out,
    float*  __restrict__ probs_out,
    float*  __restrict__ cls_out,
    int n_boxes, int prior_mod, int n_tiles)
{
    __shared__ float4 sbuf[2][BOXES_PER_TILE * PAD];   // 2 x 21504 B = 43008 B

    const int t = threadIdx.x;

    // feat_size may arrive as int32 or float32 bits; decode robustly.
    unsigned fb = *feat_raw;
    float feat = (fb < 0x01000000u) ? (float)fb : __uint_as_float(fb);
    float inv_feat = 1.0f / feat;

    const long long total_f4 = (long long)n_boxes * SLOTS;

    // prefetch lambda: issue this tile's 10 cp.asyncs into buffer `bf`
    auto prefetch = [&](int tile, int bf) {
        if (tile < n_tiles) {
            long long base = (long long)tile * TILE_F4;
            uint32_t sbase = (uint32_t)__cvta_generic_to_shared(&sbuf[bf][0]);
            #pragma unroll
            for (int r = 0; r < F4_PER_THREAD; r++) {
                int g = r * TB + t;                 // [0, 1280)
                if (base + g < total_f4) {
                    int b = g / SLOTS;
                    int s = g - b * SLOTS;
                    cp_async16(sbase + (uint32_t)(b * PAD + s) * 16u,
                               score4 + base + g);
                }
            }
        }
        cp_commit();   // always commit, keeps group accounting uniform
    };

    int tile = blockIdx.x;
    const int stride = gridDim.x;
    int bf = 0;

    prefetch(tile, 0);

    for (; tile < n_tiles; tile += stride, bf ^= 1) {
        prefetch(tile + stride, bf ^ 1);   // prefetch next (or empty commit)
        cp_wait1();                        // current tile's group complete
        __syncthreads();                   // make copies visible block-wide

        // ---- compute current tile (threads 0..63 own one box each) ----
        if (t < BOXES_PER_TILE) {
            int i = tile * BOXES_PER_TILE + t;
            if (i < n_boxes) {
                float c = conf[i];
                const float4* s = &sbuf[bf][t * PAD];
                float best = -3.402823466e+38f;
                int bidx = 0;
                #pragma unroll
                for (int j = 0; j < SLOTS; j++) {
                    float4 v = s[j];
                    float p0 = c * v.x, p1 = c * v.y,
                          p2 = c * v.z, p3 = c * v.w;
                    int base = j * 4;
                    if (p0 > best) { best = p0; bidx = base;     }
                    if (p1 > best) { best = p1; bidx = base + 1; }
                    if (p2 > best) { best = p2; bidx = base + 2; }
                    if (p3 > best) { best = p3; bidx = base + 3; }
                }

                float4 b4 = box[i];
                float4 p  = prior[i % prior_mod];
                float cx = b4.x + p.x;
                float cy = b4.y + p.y;
                float hw = 0.5f * (b4.z * p.z);
                float hh = 0.5f * (b4.w * p.w);

                float4 corners;
                corners.x = (cx - hw) * inv_feat;
                corners.y = (cy - hh) * inv_feat;
                corners.z = (cx + hw) * inv_feat;
                corners.w = (cy + hh) * inv_feat;

                bool m = best > THRESHOLD;
                box_out[i]   = m ? corners : make_float4(0.f, 0.f, 0.f, 0.f);
                probs_out[i] = m ? best : 0.0f;
                cls_out[i]   = (float)bidx;
            }
        }
        __syncthreads();   // buffer reuse fence before next prefetch lands
    }
}

extern "C" void kernel_launch(void* const* d_in, const int* in_sizes, int n_in,
                              void* d_out, int out_size)
{
    const float4*   box    = (const float4*)d_in[0];
    const float*    conf   = (const float*)d_in[1];
    const float4*   score4 = (const float4*)d_in[2];
    const float4*   prior  = (const float4*)d_in[3];
    const unsigned* feat   = (const unsigned*)d_in[4];

    int n_boxes   = in_sizes[1];       // N*HW*A
    int prior_mod = in_sizes[3] / 4;   // HW*A
    int n_tiles   = (n_boxes + BOXES_PER_TILE - 1) / BOXES_PER_TILE;

    float* out       = (float*)d_out;
    float4* box_out  = (float4*)out;
    float*  probs    = out + (size_t)n_boxes * 4;
    float*  cls      = out + (size_t)n_boxes * 5;

    int blocks = 148 * 5;              // persistent: 5 blocks/SM (43KB smem)
    if (blocks > n_tiles) blocks = n_tiles;

    detector_kernel<<<blocks, TB>>>(box, conf, score4, prior, feat,
                                    box_out, probs, cls,
                                    n_boxes, prior_mod, n_tiles);
}